// round 5
// baseline (speedup 1.0000x reference)
#include <cuda_runtime.h>
#include <cuda_bf16.h>
#include <cstdint>

#define S_LEN 128
#define T_LEN 128
#define BATCH 16
#define VOCAB 32000

// ---------------- static scratch ----------------
__device__ float g_x[2048 * 1024];       // embeddings / layer inputs
__device__ float g_xproj[2048 * 4096];   // precomputed x@Wih^T + b
__device__ float g_y[2048 * 1024];       // encoder layer0 concat outputs
__device__ float g_h0seq[2048 * 1024];   // decoder layer0 hidden sequence
__device__ float g_h1seq[2048 * 1024];   // decoder layer1 hidden sequence
__device__ float g_hA[16384], g_hB[16384];   // encoder h ping-pong [dir][b][512]
__device__ float g_encC[16384];              // encoder c
__device__ float g_dhA[16384], g_dhB[16384]; // decoder L0 h ping-pong [b][1024]
__device__ float g_dhC[16384], g_dhD[16384]; // decoder L1 h ping-pong
__device__ float g_dc0[16384], g_dc1[16384]; // decoder c per layer

// ---------------- embedding gathers ----------------
__global__ void enc_embed_kernel(const float* __restrict__ emb,
                                 const int* __restrict__ src, float* __restrict__ dst) {
    int r = blockIdx.x, t = r >> 4, b = r & 15;
    int tok = src[b * S_LEN + t];
    ((float4*)(dst + (size_t)r * 1024))[threadIdx.x] =
        ((const float4*)(emb + (size_t)tok * 1024))[threadIdx.x];
}
__global__ void dec_embed_kernel(const float* __restrict__ emb,
                                 const int* __restrict__ tgt, float* __restrict__ dst) {
    int r = blockIdx.x, s = r >> 4, b = r & 15;
    int tok = (s == 0) ? 1 : tgt[b * T_LEN + s];
    ((float4*)(dst + (size_t)r * 1024))[threadIdx.x] =
        ((const float4*)(emb + (size_t)tok * 1024))[threadIdx.x];
}

// ---------------- LSTM step: one warp per (dir,unit) ----------------
// z = xproj(row stride 4096 per batch) + h_prev @ Whh^T; gates i,f,g,o.
template <int U, int NDIR>
__global__ void __launch_bounds__(256, 1)
lstm_step_kernel(const float* __restrict__ Whh,  // [NDIR][4U][U]
                 const float* __restrict__ hin,  // [NDIR][B][U]
                 float* __restrict__ hout,
                 float* __restrict__ c,
                 const float* __restrict__ xp0,  // per-dir xproj base (+2048 col off for dir1)
                 const float* __restrict__ xp1,
                 float* __restrict__ y0,         // optional hidden store (stride 1024/row)
                 float* __restrict__ y1) {
    extern __shared__ float hs[];               // [B][U] for this block's dir
    const int tid = threadIdx.x, warp = tid >> 5, lane = tid & 31;
    const int gw = blockIdx.x * 8 + warp;
    const int dir = (NDIR == 2) ? (gw / U) : 0;
    const int u = gw - dir * U;
    {
        const float4* src4 = (const float4*)(hin + (size_t)dir * BATCH * U);
        float4* dst4 = (float4*)hs;
        for (int i = tid; i < BATCH * U / 4; i += 256) dst4[i] = src4[i];
    }
    __syncthreads();
    const float* W = Whh + (size_t)dir * 4 * U * U;
    const float* Wr0 = W + (size_t)(0 * U + u) * U;
    const float* Wr1 = W + (size_t)(1 * U + u) * U;
    const float* Wr2 = W + (size_t)(2 * U + u) * U;
    const float* Wr3 = W + (size_t)(3 * U + u) * U;
    float a0[16], a1[16], a2[16], a3[16];
#pragma unroll
    for (int b = 0; b < 16; ++b) { a0[b]=0.f; a1[b]=0.f; a2[b]=0.f; a3[b]=0.f; }
#pragma unroll 2
    for (int j = 0; j < (U >> 7); ++j) {
        const int kb = (j << 7) + (lane << 2);
        const float4 w0 = *(const float4*)(Wr0 + kb);
        const float4 w1 = *(const float4*)(Wr1 + kb);
        const float4 w2 = *(const float4*)(Wr2 + kb);
        const float4 w3 = *(const float4*)(Wr3 + kb);
#pragma unroll
        for (int b = 0; b < 16; ++b) {
            const float4 h4 = *(const float4*)(hs + b * U + kb);
            a0[b] += w0.x*h4.x + w0.y*h4.y + w0.z*h4.z + w0.w*h4.w;
            a1[b] += w1.x*h4.x + w1.y*h4.y + w1.z*h4.z + w1.w*h4.w;
            a2[b] += w2.x*h4.x + w2.y*h4.y + w2.z*h4.z + w2.w*h4.w;
            a3[b] += w3.x*h4.x + w3.y*h4.y + w3.z*h4.z + w3.w*h4.w;
        }
    }
#pragma unroll
    for (int b = 0; b < 16; ++b)
#pragma unroll
        for (int off = 16; off > 0; off >>= 1) {
            a0[b] += __shfl_xor_sync(0xffffffffu, a0[b], off);
            a1[b] += __shfl_xor_sync(0xffffffffu, a1[b], off);
            a2[b] += __shfl_xor_sync(0xffffffffu, a2[b], off);
            a3[b] += __shfl_xor_sync(0xffffffffu, a3[b], off);
        }
    if (lane < 16) {
        const int b = lane;
        const float* xp = ((dir == 0) ? xp0 : xp1) + (size_t)b * 4096;
        const float zi = a0[b] + xp[0 * U + u];
        const float zf = a1[b] + xp[1 * U + u];
        const float zg = a2[b] + xp[2 * U + u];
        const float zo = a3[b] + xp[3 * U + u];
        const float ig = 1.f / (1.f + __expf(-zi));
        const float fg = 1.f / (1.f + __expf(-zf));
        const float gg = tanhf(zg);
        const float og = 1.f / (1.f + __expf(-zo));
        const size_t idx = (size_t)dir * BATCH * U + (size_t)b * U + u;
        const float cn = fg * c[idx] + ig * gg;
        c[idx] = cn;
        const float hn = og * tanhf(cn);
        hout[idx] = hn;
        float* y = (dir == 0) ? y0 : y1;
        if (y) y[(size_t)b * 1024 + u] = hn;
    }
}

// ---------------- GEMM (NT): C[m,n] = A[m,:]·B[n,:] + bias[n] ----------------
__global__ void __launch_bounds__(256)
gemm_nt_kernel(const float* __restrict__ A, const float* __restrict__ B,
               const float* __restrict__ bias, float* __restrict__ C,
               int M, int N, int K, int fcmode) {
    __shared__ float As[16][128];
    __shared__ float Bs[16][128];
    const int tid = threadIdx.x, bx = blockIdx.x, by = blockIdx.y;
    const int lr = tid >> 1, lk = (tid & 1) << 3;
    const int tx = tid & 15, ty = tid >> 4;
    const float* Aload = A + (size_t)(by * 128 + lr) * K + lk;
    const float* Bload = B + (size_t)(bx * 128 + lr) * K + lk;
    float acc[8][8];
#pragma unroll
    for (int i = 0; i < 8; ++i)
#pragma unroll
        for (int j = 0; j < 8; ++j) acc[i][j] = 0.f;
    for (int k0 = 0; k0 < K; k0 += 16) {
        const float4 av0 = *(const float4*)(Aload + k0);
        const float4 av1 = *(const float4*)(Aload + k0 + 4);
        const float4 bv0 = *(const float4*)(Bload + k0);
        const float4 bv1 = *(const float4*)(Bload + k0 + 4);
        __syncthreads();
        As[lk+0][lr]=av0.x; As[lk+1][lr]=av0.y; As[lk+2][lr]=av0.z; As[lk+3][lr]=av0.w;
        As[lk+4][lr]=av1.x; As[lk+5][lr]=av1.y; As[lk+6][lr]=av1.z; As[lk+7][lr]=av1.w;
        Bs[lk+0][lr]=bv0.x; Bs[lk+1][lr]=bv0.y; Bs[lk+2][lr]=bv0.z; Bs[lk+3][lr]=bv0.w;
        Bs[lk+4][lr]=bv1.x; Bs[lk+5][lr]=bv1.y; Bs[lk+6][lr]=bv1.z; Bs[lk+7][lr]=bv1.w;
        __syncthreads();
#pragma unroll
        for (int kk = 0; kk < 16; ++kk) {
            const float4 af0 = *(const float4*)&As[kk][ty * 4];
            const float4 af1 = *(const float4*)&As[kk][64 + ty * 4];
            const float4 bf0 = *(const float4*)&Bs[kk][tx * 4];
            const float4 bf1 = *(const float4*)&Bs[kk][64 + tx * 4];
            const float am[8] = {af0.x,af0.y,af0.z,af0.w,af1.x,af1.y,af1.z,af1.w};
            const float bn[8] = {bf0.x,bf0.y,bf0.z,bf0.w,bf1.x,bf1.y,bf1.z,bf1.w};
#pragma unroll
            for (int i = 0; i < 8; ++i)
#pragma unroll
                for (int j = 0; j < 8; ++j) acc[i][j] += am[i] * bn[j];
        }
    }
#pragma unroll
    for (int i = 0; i < 8; ++i) {
        const int msub = (i < 4) ? (ty * 4 + i) : (64 + ty * 4 + i - 4);
        const int m = by * 128 + msub;
        if (m >= M) continue;
#pragma unroll
        for (int j = 0; j < 8; ++j) {
            const int nsub = (j < 4) ? (tx * 4 + j) : (64 + tx * 4 + j - 4);
            const int n = bx * 128 + nsub;
            const float v = acc[i][j] + bias[n];
            if (fcmode) {
                const int b = m & 15, t = (m >> 4) + 1;
                C[(size_t)b * T_LEN * VOCAB + (size_t)t * VOCAB + n] = v;
            } else {
                C[(size_t)m * N + n] = v;
            }
        }
    }
}

// encoder [dir][b][512] -> decoder [b][1024] (concat fwd/bwd), for h and c
__global__ void concat_hc_kernel(const float* __restrict__ hsrc, const float* __restrict__ csrc,
                                 float* __restrict__ hdst, float* __restrict__ cdst) {
    const int idx = blockIdx.x * 256 + threadIdx.x;   // 16384
    const int b = idx >> 10, col = idx & 1023;
    const int dir = col >> 9, u = col & 511;
    const int s = dir * 8192 + b * 512 + u;
    hdst[idx] = hsrc[s];
    cdst[idx] = csrc[s];
}

__global__ void zero_t0_kernel(float* __restrict__ out) {
    const int idx = blockIdx.x * 256 + threadIdx.x;   // 16*32000
    if (idx < 16 * VOCAB) {
        const int b = idx / VOCAB, v = idx - b * VOCAB;
        out[(size_t)b * T_LEN * VOCAB + v] = 0.f;
    }
}

// ---------------- driver ----------------
extern "C" void kernel_launch(void* const* d_in, const int* in_sizes, int n_in,
                              void* d_out, int out_size) {
    (void)in_sizes; (void)n_in; (void)out_size;
    const int*   src       = (const int*)d_in[0];
    const int*   tgt       = (const int*)d_in[1];
    const float* enc_embed = (const float*)d_in[3];
    const float* enc_Wih   = (const float*)d_in[4];   // [2][2][2048][1024]
    const float* enc_Whh   = (const float*)d_in[5];   // [2][2][2048][512]
    const float* enc_b     = (const float*)d_in[6];   // [2][2][2048]
    const float* dec_embed = (const float*)d_in[7];
    const float* dec_Wih   = (const float*)d_in[8];   // [2][4096][1024]
    const float* dec_Whh   = (const float*)d_in[9];   // [2][4096][1024]
    const float* dec_b     = (const float*)d_in[10];  // [2][4096]
    const float* fc_W      = (const float*)d_in[11];  // [32000][1024]
    const float* fc_b      = (const float*)d_in[12];  // [32000]
    float* out = (float*)d_out;

    float *x, *xp, *y, *h0s, *h1s, *hA, *hB, *eC, *dA, *dB, *dC, *dD, *c0, *c1;
    cudaGetSymbolAddress((void**)&x, g_x);
    cudaGetSymbolAddress((void**)&xp, g_xproj);
    cudaGetSymbolAddress((void**)&y, g_y);
    cudaGetSymbolAddress((void**)&h0s, g_h0seq);
    cudaGetSymbolAddress((void**)&h1s, g_h1seq);
    cudaGetSymbolAddress((void**)&hA, g_hA);
    cudaGetSymbolAddress((void**)&hB, g_hB);
    cudaGetSymbolAddress((void**)&eC, g_encC);
    cudaGetSymbolAddress((void**)&dA, g_dhA);
    cudaGetSymbolAddress((void**)&dB, g_dhB);
    cudaGetSymbolAddress((void**)&dC, g_dhC);
    cudaGetSymbolAddress((void**)&dD, g_dhD);
    cudaGetSymbolAddress((void**)&c0, g_dc0);
    cudaGetSymbolAddress((void**)&c1, g_dc1);

    cudaFuncSetAttribute(lstm_step_kernel<512, 2>,
                         cudaFuncAttributeMaxDynamicSharedMemorySize, 32768);
    cudaFuncSetAttribute(lstm_step_kernel<1024, 1>,
                         cudaFuncAttributeMaxDynamicSharedMemorySize, 65536);

    // ===== Encoder =====
    enc_embed_kernel<<<2048, 256>>>(enc_embed, src, x);
    for (int l = 0; l < 2; ++l) {
        cudaMemsetAsync(hA, 0, 16384 * sizeof(float));
        cudaMemsetAsync(eC, 0, 16384 * sizeof(float));
        const float* Ain = (l == 0) ? x : y;
        gemm_nt_kernel<<<dim3(32, 16), 256>>>(
            Ain, enc_Wih + (size_t)l * 2 * 2048 * 1024, enc_b + l * 4096, xp,
            2048, 4096, 1024, 0);
        const float* Whh_l = enc_Whh + (size_t)l * 2 * 2048 * 512;
        for (int j = 0; j < 128; ++j) {
            float* hin  = (j & 1) ? hB : hA;
            float* hout = (j & 1) ? hA : hB;
            const float* xp0 = xp + (size_t)j * 16 * 4096;
            const float* xp1 = xp + (size_t)(127 - j) * 16 * 4096 + 2048;
            float* y0 = (l == 0) ? (y + (size_t)j * 16 * 1024) : nullptr;
            float* y1 = (l == 0) ? (y + (size_t)(127 - j) * 16 * 1024 + 512) : nullptr;
            lstm_step_kernel<512, 2><<<128, 256, 32768>>>(
                Whh_l, hin, hout, eC, xp0, xp1, y0, y1);
        }
        // final h in hA (step 127 writes hA); build decoder layer-l init
        float* hdst = (l == 0) ? dA : dC;
        float* cdst = (l == 0) ? c0 : c1;
        concat_hc_kernel<<<64, 256>>>(hA, eC, hdst, cdst);
    }

    // ===== Decoder =====
    dec_embed_kernel<<<2032, 256>>>(dec_embed, tgt, x);
    // layer 0
    gemm_nt_kernel<<<dim3(32, 16), 256>>>(
        x, dec_Wih, dec_b, xp, 2032, 4096, 1024, 0);
    for (int s = 0; s < 127; ++s) {
        float* hin  = (s & 1) ? dB : dA;
        float* hout = (s & 1) ? dA : dB;
        lstm_step_kernel<1024, 1><<<128, 256, 65536>>>(
            dec_Whh, hin, hout, c0, xp + (size_t)s * 16 * 4096, nullptr,
            h0s + (size_t)s * 16 * 1024, nullptr);
    }
    // layer 1
    gemm_nt_kernel<<<dim3(32, 16), 256>>>(
        h0s, dec_Wih + (size_t)4096 * 1024, dec_b + 4096, xp, 2032, 4096, 1024, 0);
    const float* Whh1 = dec_Whh + (size_t)4096 * 1024;
    for (int s = 0; s < 127; ++s) {
        float* hin  = (s & 1) ? dD : dC;
        float* hout = (s & 1) ? dC : dD;
        lstm_step_kernel<1024, 1><<<128, 256, 65536>>>(
            Whh1, hin, hout, c1, xp + (size_t)s * 16 * 4096, nullptr,
            h1s + (size_t)s * 16 * 1024, nullptr);
    }

    // ===== Output =====
    zero_t0_kernel<<<2000, 256>>>(out);
    gemm_nt_kernel<<<dim3(250, 16), 256>>>(
        h1s, fc_W, fc_b, out, 2032, VOCAB, 1024, 1);
}

// round 6
// speedup vs baseline: 1.5469x; 1.5469x over previous
#include <cuda_runtime.h>
#include <cuda_bf16.h>
#include <cstdint>

#define S_LEN 128
#define T_LEN 128
#define BATCH 16
#define VOCAB 32000

// ---------------- static scratch ----------------
__device__ float g_x[2048 * 1024];       // embeddings / layer inputs
__device__ float g_xproj[2048 * 4096];   // precomputed x@Wih^T + b
__device__ float g_y[2048 * 1024];       // encoder layer0 concat outputs
__device__ float g_h0seq[2048 * 1024];   // decoder layer0 hidden sequence
__device__ float g_h1seq[2048 * 1024];   // decoder layer1 hidden sequence
__device__ float g_hA[16384], g_hB[16384];   // encoder h ping-pong [dir][b][512]
__device__ float g_encC[16384];              // encoder c
__device__ float g_dhA[16384], g_dhB[16384]; // decoder L0 h ping-pong [b][1024]
__device__ float g_dhC[16384], g_dhD[16384]; // decoder L1 h ping-pong
__device__ float g_dc0[16384], g_dc1[16384]; // decoder c per layer

// ---------------- embedding gathers ----------------
__global__ void enc_embed_kernel(const float* __restrict__ emb,
                                 const int* __restrict__ src, float* __restrict__ dst) {
    int r = blockIdx.x, t = r >> 4, b = r & 15;
    int tok = src[b * S_LEN + t];
    ((float4*)(dst + (size_t)r * 1024))[threadIdx.x] =
        ((const float4*)(emb + (size_t)tok * 1024))[threadIdx.x];
}
__global__ void dec_embed_kernel(const float* __restrict__ emb,
                                 const int* __restrict__ tgt, float* __restrict__ dst) {
    int r = blockIdx.x, s = r >> 4, b = r & 15;
    int tok = (s == 0) ? 1 : tgt[b * T_LEN + s];
    ((float4*)(dst + (size_t)r * 1024))[threadIdx.x] =
        ((const float4*)(emb + (size_t)tok * 1024))[threadIdx.x];
}

// ---------------- LSTM step: one warp per (dir,unit) ----------------
// z = xproj(row stride 4096 per batch) + h_prev @ Whh^T; gates i,f,g,o.
template <int U, int NDIR>
__global__ void __launch_bounds__(256, 1)
lstm_step_kernel(const float* __restrict__ Whh,  // [NDIR][4U][U]
                 const float* __restrict__ hin,  // [NDIR][B][U]
                 float* __restrict__ hout,
                 float* __restrict__ c,
                 const float* __restrict__ xp0,  // per-dir xproj base (+2048 col off for dir1)
                 const float* __restrict__ xp1,
                 float* __restrict__ y0,         // optional hidden store (stride 1024/row)
                 float* __restrict__ y1) {
    extern __shared__ float hs[];               // [B][U] for this block's dir
    const int tid = threadIdx.x, warp = tid >> 5, lane = tid & 31;
    const int gw = blockIdx.x * 8 + warp;
    const int dir = (NDIR == 2) ? (gw / U) : 0;
    const int u = gw - dir * U;
    {
        const float4* src4 = (const float4*)(hin + (size_t)dir * BATCH * U);
        float4* dst4 = (float4*)hs;
        for (int i = tid; i < BATCH * U / 4; i += 256) dst4[i] = src4[i];
    }
    __syncthreads();
    const float* W = Whh + (size_t)dir * 4 * U * U;
    const float* Wr0 = W + (size_t)(0 * U + u) * U;
    const float* Wr1 = W + (size_t)(1 * U + u) * U;
    const float* Wr2 = W + (size_t)(2 * U + u) * U;
    const float* Wr3 = W + (size_t)(3 * U + u) * U;
    float a0[16], a1[16], a2[16], a3[16];
#pragma unroll
    for (int b = 0; b < 16; ++b) { a0[b]=0.f; a1[b]=0.f; a2[b]=0.f; a3[b]=0.f; }
#pragma unroll 2
    for (int j = 0; j < (U >> 7); ++j) {
        const int kb = (j << 7) + (lane << 2);
        const float4 w0 = *(const float4*)(Wr0 + kb);
        const float4 w1 = *(const float4*)(Wr1 + kb);
        const float4 w2 = *(const float4*)(Wr2 + kb);
        const float4 w3 = *(const float4*)(Wr3 + kb);
#pragma unroll
        for (int b = 0; b < 16; ++b) {
            const float4 h4 = *(const float4*)(hs + b * U + kb);
            a0[b] += w0.x*h4.x + w0.y*h4.y + w0.z*h4.z + w0.w*h4.w;
            a1[b] += w1.x*h4.x + w1.y*h4.y + w1.z*h4.z + w1.w*h4.w;
            a2[b] += w2.x*h4.x + w2.y*h4.y + w2.z*h4.z + w2.w*h4.w;
            a3[b] += w3.x*h4.x + w3.y*h4.y + w3.z*h4.z + w3.w*h4.w;
        }
    }
#pragma unroll
    for (int b = 0; b < 16; ++b)
#pragma unroll
        for (int off = 16; off > 0; off >>= 1) {
            a0[b] += __shfl_xor_sync(0xffffffffu, a0[b], off);
            a1[b] += __shfl_xor_sync(0xffffffffu, a1[b], off);
            a2[b] += __shfl_xor_sync(0xffffffffu, a2[b], off);
            a3[b] += __shfl_xor_sync(0xffffffffu, a3[b], off);
        }
    if (lane < 16) {
        const int b = lane;
        const float* xp = ((dir == 0) ? xp0 : xp1) + (size_t)b * 4096;
        const float zi = a0[b] + xp[0 * U + u];
        const float zf = a1[b] + xp[1 * U + u];
        const float zg = a2[b] + xp[2 * U + u];
        const float zo = a3[b] + xp[3 * U + u];
        const float ig = 1.f / (1.f + __expf(-zi));
        const float fg = 1.f / (1.f + __expf(-zf));
        const float gg = tanhf(zg);
        const float og = 1.f / (1.f + __expf(-zo));
        const size_t idx = (size_t)dir * BATCH * U + (size_t)b * U + u;
        const float cn = fg * c[idx] + ig * gg;
        c[idx] = cn;
        const float hn = og * tanhf(cn);
        hout[idx] = hn;
        float* y = (dir == 0) ? y0 : y1;
        if (y) y[(size_t)b * 1024 + u] = hn;
    }
}

// ---------------- GEMM (NT): C[m,n] = A[m,:]·B[n,:] + bias[n] ----------------
__global__ void __launch_bounds__(256)
gemm_nt_kernel(const float* __restrict__ A, const float* __restrict__ B,
               const float* __restrict__ bias, float* __restrict__ C,
               int M, int N, int K, int fcmode) {
    __shared__ float As[16][128];
    __shared__ float Bs[16][128];
    const int tid = threadIdx.x, bx = blockIdx.x, by = blockIdx.y;
    const int lr = tid >> 1, lk = (tid & 1) << 3;
    const int tx = tid & 15, ty = tid >> 4;
    const float* Aload = A + (size_t)(by * 128 + lr) * K + lk;
    const float* Bload = B + (size_t)(bx * 128 + lr) * K + lk;
    float acc[8][8];
#pragma unroll
    for (int i = 0; i < 8; ++i)
#pragma unroll
        for (int j = 0; j < 8; ++j) acc[i][j] = 0.f;
    for (int k0 = 0; k0 < K; k0 += 16) {
        const float4 av0 = *(const float4*)(Aload + k0);
        const float4 av1 = *(const float4*)(Aload + k0 + 4);
        const float4 bv0 = *(const float4*)(Bload + k0);
        const float4 bv1 = *(const float4*)(Bload + k0 + 4);
        __syncthreads();
        As[lk+0][lr]=av0.x; As[lk+1][lr]=av0.y; As[lk+2][lr]=av0.z; As[lk+3][lr]=av0.w;
        As[lk+4][lr]=av1.x; As[lk+5][lr]=av1.y; As[lk+6][lr]=av1.z; As[lk+7][lr]=av1.w;
        Bs[lk+0][lr]=bv0.x; Bs[lk+1][lr]=bv0.y; Bs[lk+2][lr]=bv0.z; Bs[lk+3][lr]=bv0.w;
        Bs[lk+4][lr]=bv1.x; Bs[lk+5][lr]=bv1.y; Bs[lk+6][lr]=bv1.z; Bs[lk+7][lr]=bv1.w;
        __syncthreads();
#pragma unroll
        for (int kk = 0; kk < 16; ++kk) {
            const float4 af0 = *(const float4*)&As[kk][ty * 4];
            const float4 af1 = *(const float4*)&As[kk][64 + ty * 4];
            const float4 bf0 = *(const float4*)&Bs[kk][tx * 4];
            const float4 bf1 = *(const float4*)&Bs[kk][64 + tx * 4];
            const float am[8] = {af0.x,af0.y,af0.z,af0.w,af1.x,af1.y,af1.z,af1.w};
            const float bn[8] = {bf0.x,bf0.y,bf0.z,bf0.w,bf1.x,bf1.y,bf1.z,bf1.w};
#pragma unroll
            for (int i = 0; i < 8; ++i)
#pragma unroll
                for (int j = 0; j < 8; ++j) acc[i][j] += am[i] * bn[j];
        }
    }
#pragma unroll
    for (int i = 0; i < 8; ++i) {
        const int msub = (i < 4) ? (ty * 4 + i) : (64 + ty * 4 + i - 4);
        const int m = by * 128 + msub;
        if (m >= M) continue;
#pragma unroll
        for (int j = 0; j < 8; ++j) {
            const int nsub = (j < 4) ? (tx * 4 + j) : (64 + tx * 4 + j - 4);
            const int n = bx * 128 + nsub;
            const float v = acc[i][j] + bias[n];
            if (fcmode) {
                const int b = m & 15, t = (m >> 4) + 1;
                C[(size_t)b * T_LEN * VOCAB + (size_t)t * VOCAB + n] = v;
            } else {
                C[(size_t)m * N + n] = v;
            }
        }
    }
}

// encoder [dir][b][512] -> decoder [b][1024] (concat fwd/bwd), for h and c
__global__ void concat_hc_kernel(const float* __restrict__ hsrc, const float* __restrict__ csrc,
                                 float* __restrict__ hdst, float* __restrict__ cdst) {
    const int idx = blockIdx.x * 256 + threadIdx.x;   // 16384
    const int b = idx >> 10, col = idx & 1023;
    const int dir = col >> 9, u = col & 511;
    const int s = dir * 8192 + b * 512 + u;
    hdst[idx] = hsrc[s];
    cdst[idx] = csrc[s];
}

__global__ void zero_t0_kernel(float* __restrict__ out) {
    const int idx = blockIdx.x * 256 + threadIdx.x;   // 16*32000
    if (idx < 16 * VOCAB) {
        const int b = idx / VOCAB, v = idx - b * VOCAB;
        out[(size_t)b * T_LEN * VOCAB + v] = 0.f;
    }
}

// ---------------- driver ----------------
extern "C" void kernel_launch(void* const* d_in, const int* in_sizes, int n_in,
                              void* d_out, int out_size) {
    (void)in_sizes; (void)n_in; (void)out_size;
    const int*   src       = (const int*)d_in[0];
    const int*   tgt       = (const int*)d_in[1];
    const float* enc_embed = (const float*)d_in[3];
    const float* enc_Wih   = (const float*)d_in[4];   // [2][2][2048][1024]
    const float* enc_Whh   = (const float*)d_in[5];   // [2][2][2048][512]
    const float* enc_b     = (const float*)d_in[6];   // [2][2][2048]
    const float* dec_embed = (const float*)d_in[7];
    const float* dec_Wih   = (const float*)d_in[8];   // [2][4096][1024]
    const float* dec_Whh   = (const float*)d_in[9];   // [2][4096][1024]
    const float* dec_b     = (const float*)d_in[10];  // [2][4096]
    const float* fc_W      = (const float*)d_in[11];  // [32000][1024]
    const float* fc_b      = (const float*)d_in[12];  // [32000]
    float* out = (float*)d_out;

    float *x, *xp, *y, *h0s, *h1s, *hA, *hB, *eC, *dA, *dB, *dC, *dD, *c0, *c1;
    cudaGetSymbolAddress((void**)&x, g_x);
    cudaGetSymbolAddress((void**)&xp, g_xproj);
    cudaGetSymbolAddress((void**)&y, g_y);
    cudaGetSymbolAddress((void**)&h0s, g_h0seq);
    cudaGetSymbolAddress((void**)&h1s, g_h1seq);
    cudaGetSymbolAddress((void**)&hA, g_hA);
    cudaGetSymbolAddress((void**)&hB, g_hB);
    cudaGetSymbolAddress((void**)&eC, g_encC);
    cudaGetSymbolAddress((void**)&dA, g_dhA);
    cudaGetSymbolAddress((void**)&dB, g_dhB);
    cudaGetSymbolAddress((void**)&dC, g_dhC);
    cudaGetSymbolAddress((void**)&dD, g_dhD);
    cudaGetSymbolAddress((void**)&c0, g_dc0);
    cudaGetSymbolAddress((void**)&c1, g_dc1);

    cudaFuncSetAttribute(lstm_step_kernel<512, 2>,
                         cudaFuncAttributeMaxDynamicSharedMemorySize, 32768);
    cudaFuncSetAttribute(lstm_step_kernel<1024, 1>,
                         cudaFuncAttributeMaxDynamicSharedMemorySize, 65536);

    // ===== Encoder =====
    enc_embed_kernel<<<2048, 256>>>(enc_embed, src, x);
    for (int l = 0; l < 2; ++l) {
        cudaMemsetAsync(hA, 0, 16384 * sizeof(float));
        cudaMemsetAsync(eC, 0, 16384 * sizeof(float));
        const float* Ain = (l == 0) ? x : y;
        gemm_nt_kernel<<<dim3(32, 16), 256>>>(
            Ain, enc_Wih + (size_t)l * 2 * 2048 * 1024, enc_b + l * 4096, xp,
            2048, 4096, 1024, 0);
        const float* Whh_l = enc_Whh + (size_t)l * 2 * 2048 * 512;
        for (int j = 0; j < 128; ++j) {
            float* hin  = (j & 1) ? hB : hA;
            float* hout = (j & 1) ? hA : hB;
            const float* xp0 = xp + (size_t)j * 16 * 4096;
            const float* xp1 = xp + (size_t)(127 - j) * 16 * 4096 + 2048;
            float* y0 = (l == 0) ? (y + (size_t)j * 16 * 1024) : nullptr;
            float* y1 = (l == 0) ? (y + (size_t)(127 - j) * 16 * 1024 + 512) : nullptr;
            lstm_step_kernel<512, 2><<<128, 256, 32768>>>(
                Whh_l, hin, hout, eC, xp0, xp1, y0, y1);
        }
        // final h in hA (step 127 writes hA); build decoder layer-l init
        float* hdst = (l == 0) ? dA : dC;
        float* cdst = (l == 0) ? c0 : c1;
        concat_hc_kernel<<<64, 256>>>(hA, eC, hdst, cdst);
    }

    // ===== Decoder =====
    dec_embed_kernel<<<2032, 256>>>(dec_embed, tgt, x);
    // layer 0
    gemm_nt_kernel<<<dim3(32, 16), 256>>>(
        x, dec_Wih, dec_b, xp, 2032, 4096, 1024, 0);
    for (int s = 0; s < 127; ++s) {
        float* hin  = (s & 1) ? dB : dA;
        float* hout = (s & 1) ? dA : dB;
        lstm_step_kernel<1024, 1><<<128, 256, 65536>>>(
            dec_Whh, hin, hout, c0, xp + (size_t)s * 16 * 4096, nullptr,
            h0s + (size_t)s * 16 * 1024, nullptr);
    }
    // layer 1
    gemm_nt_kernel<<<dim3(32, 16), 256>>>(
        h0s, dec_Wih + (size_t)4096 * 1024, dec_b + 4096, xp, 2032, 4096, 1024, 0);
    const float* Whh1 = dec_Whh + (size_t)4096 * 1024;
    for (int s = 0; s < 127; ++s) {
        float* hin  = (s & 1) ? dD : dC;
        float* hout = (s & 1) ? dC : dD;
        lstm_step_kernel<1024, 1><<<128, 256, 65536>>>(
            Whh1, hin, hout, c1, xp + (size_t)s * 16 * 4096, nullptr,
            h1s + (size_t)s * 16 * 1024, nullptr);
    }

    // ===== Output =====
    zero_t0_kernel<<<2000, 256>>>(out);
    gemm_nt_kernel<<<dim3(250, 16), 256>>>(
        h1s, fc_W, fc_b, out, 2032, VOCAB, 1024, 1);
}